// round 6
// baseline (speedup 1.0000x reference)
#include <cuda_runtime.h>
#include <cuda_bf16.h>
#include <cstdint>

#define NN   65536
#define EE   524288
#define DIN  128
#define HD   256
#define NB   8
#define MROW 2048   // NB * HD

// ======================= helpers =======================
__device__ __forceinline__ void split_bf16(float v, __nv_bfloat16& h, __nv_bfloat16& l) {
    h = __float2bfloat16(v);
    l = __float2bfloat16(v - __bfloat162float(h));
}

__device__ __forceinline__ void mma16816(float* c, const uint32_t* a, const uint32_t* b) {
    asm volatile(
        "mma.sync.aligned.m16n8k16.row.col.f32.bf16.bf16.f32 "
        "{%0,%1,%2,%3}, {%4,%5,%6,%7}, {%8,%9}, {%0,%1,%2,%3};"
        : "+f"(c[0]), "+f"(c[1]), "+f"(c[2]), "+f"(c[3])
        : "r"(a[0]), "r"(a[1]), "r"(a[2]), "r"(a[3]), "r"(b[0]), "r"(b[1]));
}

__device__ __forceinline__ void ldsm4(uint32_t* r, uint32_t addr) {
    asm volatile("ldmatrix.sync.aligned.m8n8.x4.shared.b16 {%0,%1,%2,%3}, [%4];"
        : "=r"(r[0]), "=r"(r[1]), "=r"(r[2]), "=r"(r[3]) : "r"(addr));
}

__device__ __forceinline__ uint32_t smem_u32(const void* p) {
    uint32_t a;
    asm("{ .reg .u64 t; cvta.to.shared.u64 t, %1; cvt.u32.u64 %0, t; }" : "=r"(a) : "l"(p));
    return a;
}

__device__ __forceinline__ void cpa16(uint32_t dst, const void* src) {
    asm volatile("cp.async.cg.shared.global [%0], [%1], 16;" :: "r"(dst), "l"(src));
}
#define CPA_COMMIT() asm volatile("cp.async.commit_group;" ::: "memory")
#define CPA_WAIT1()  asm volatile("cp.async.wait_group 1;" ::: "memory")
#define CPA_WAIT0()  asm volatile("cp.async.wait_group 0;" ::: "memory")

// smem stage: Ah, Al (128 x 32) + Bh, Bl (256 x 32), rows padded to 40 bf16
#define TSTRIDE 40
#define ATE (128 * TSTRIDE)
#define BTE (256 * TSTRIDE)
#define OFF_AH 0
#define OFF_AL (ATE * 2)
#define OFF_BH (2 * ATE * 2)
#define OFF_BL (2 * ATE * 2 + BTE * 2)
#define STAGE_BYTES ((2 * ATE + 2 * BTE) * 2)       // 61440
#define GEMM_SMEM_BYTES (2 * STAGE_BYTES)           // 122880

// ======================= static device scratch =======================
__device__ __nv_bfloat16 d_h02[NN * 256];
__device__ __nv_bfloat16 d_agg2[NN * 512];
__device__ __nv_bfloat16 d_h2A[NN * 512];
__device__ __nv_bfloat16 d_h2B[NN * 512];
__device__ __nv_bfloat16 d_m1A2[(size_t)MROW * 16384];
__device__ __nv_bfloat16 d_w2[8][256 * 512];
__device__ __nv_bfloat16 d_m1w2[(size_t)256 * 16384];
__device__ int   d_cnt[NN];
__device__ int   d_off[NN + 1];
__device__ int   d_cur[NN];
__device__ int   d_csr[EE];
__device__ float d_invcnt[NN];
__device__ float d_m1[MROW * HD];
__device__ float d_y[MROW];
__device__ float d_ybn[NB * HD];
__device__ float d_z[NB * HD];

// ======================= small kernels =======================
__global__ void zero_f(float* __restrict__ p, int n) {
    int i = blockIdx.x * blockDim.x + threadIdx.x;
    if (i < n) p[i] = 0.0f;
}
__global__ void zero_i(int* __restrict__ p, int n) {
    int i = blockIdx.x * blockDim.x + threadIdx.x;
    if (i < n) p[i] = 0;
}

__global__ void concat2_kernel(const float* __restrict__ x, const float* __restrict__ g0,
                               const float* __restrict__ g1, const float* __restrict__ g2) {
    int i = blockIdx.x * blockDim.x + threadIdx.x;
    if (i >= NN * 128) return;
    int n = i >> 7, j = i & 127;
    float v;
    if (j < 32)       v = x[n * 32 + j];
    else if (j < 64)  v = g0[n * 32 + (j - 32)];
    else if (j < 96)  v = g1[n * 32 + (j - 64)];
    else              v = g2[n * 32 + (j - 96)];
    __nv_bfloat16 h, l; split_bf16(v, h, l);
    d_h02[n * 256 + j]       = h;
    d_h02[n * 256 + 128 + j] = l;
}

__global__ void conv_w(const float* __restrict__ W, __nv_bfloat16* __restrict__ out, int K) {
    int i = blockIdx.x * blockDim.x + threadIdx.x;
    if (i >= K * 256) return;
    int n = i & 255, k = i >> 8;
    float v = W[k * 256 + n];
    __nv_bfloat16 h, l; split_bf16(v, h, l);
    out[(size_t)n * 2 * K + k]     = h;
    out[(size_t)n * 2 * K + K + k] = l;
}

__global__ void count_kernel(const int* __restrict__ dst) {
    int e = blockIdx.x * blockDim.x + threadIdx.x;
    if (e < EE) atomicAdd(&d_cnt[dst[e]], 1);
}

__global__ void invcnt_kernel() {
    int n = blockIdx.x * blockDim.x + threadIdx.x;
    if (n < NN) d_invcnt[n] = 1.0f / fmaxf((float)d_cnt[n], 1.0f);
}

__global__ void scan_kernel() {
    __shared__ int s[1024];
    int t = threadIdx.x;
    int base = t * 64;
    int sum = 0;
    for (int i = 0; i < 64; i++) sum += d_cnt[base + i];
    s[t] = sum;
    __syncthreads();
    for (int o = 1; o < 1024; o <<= 1) {
        int v = (t >= o) ? s[t - o] : 0;
        __syncthreads();
        s[t] += v;
        __syncthreads();
    }
    int run = s[t] - sum;
    for (int i = 0; i < 64; i++) { d_off[base + i] = run; run += d_cnt[base + i]; }
    if (t == 1023) d_off[NN] = run;
}

__global__ void fill_kernel(const int* __restrict__ src, const int* __restrict__ dst) {
    int e = blockIdx.x * blockDim.x + threadIdx.x;
    if (e >= EE) return;
    int d = dst[e];
    int p = atomicAdd(&d_cur[d], 1);
    d_csr[d_off[d] + p] = src[e];
}

// CSR mean-aggregation: warp per node. Rows are [hi(D) | lo(D)] bf16.
template <int D>
__global__ void agg_csr(const __nv_bfloat16* __restrict__ H2,
                        __nv_bfloat16* __restrict__ out2) {
    int w = (blockIdx.x * blockDim.x + threadIdx.x) >> 5;
    int lane = threadIdx.x & 31;
    if (w >= NN) return;
    int s0 = __ldg(&d_off[w]), s1 = __ldg(&d_off[w + 1]);
    constexpr int R = D / 64;
    float a0[R], a1[R];
#pragma unroll
    for (int r = 0; r < R; r++) { a0[r] = 0.0f; a1[r] = 0.0f; }
    for (int p = s0; p < s1; p++) {
        int nb = __ldg(&d_csr[p]);
        const __nv_bfloat16* base = H2 + (size_t)nb * (2 * D);
#pragma unroll
        for (int r = 0; r < R; r++) {
            int c2 = (lane + r * 32) * 2;
            __nv_bfloat162 hv = *reinterpret_cast<const __nv_bfloat162*>(base + c2);
            __nv_bfloat162 lv = *reinterpret_cast<const __nv_bfloat162*>(base + D + c2);
            float2 hf = __bfloat1622float2(hv);
            float2 lf = __bfloat1622float2(lv);
            a0[r] += hf.x + lf.x;
            a1[r] += hf.y + lf.y;
        }
    }
    float ic = d_invcnt[w];
    __nv_bfloat16* ob = out2 + (size_t)w * (2 * D);
#pragma unroll
    for (int r = 0; r < R; r++) {
        float v0 = a0[r] * ic, v1 = a1[r] * ic;
        __nv_bfloat16 h0, l0, h1, l1;
        split_bf16(v0, h0, l0);
        split_bf16(v1, h1, l1);
        int c2 = (lane + r * 32) * 2;
        *reinterpret_cast<__nv_bfloat162*>(ob + c2)     = __nv_bfloat162{h0, h1};
        *reinterpret_cast<__nv_bfloat162*>(ob + D + c2) = __nv_bfloat162{l0, l1};
    }
}

// ======================= GEMM compute core (ldmatrix + 3-term split) ==============
// Block: 512 threads, 16 warps (4m x 4n). Warp tile 32 x 64. Chunk = 32 K-cols.
__device__ __forceinline__ void gemm_chunk(uint32_t stage, int wm, int wn, int lane,
                                           float acc[2][8][4]) {
    // A frag addr: lanes 0-15 -> rows, 16-31 -> +8 cols
    const uint32_t aBase = stage + OFF_AH +
        (uint32_t)(((wm * 32 + (lane & 15)) * TSTRIDE + (lane >> 4) * 8) * 2);
    // B frag addr: lanes {0-7,8-15,16-23,24-31} -> (n0-7,k0-7),(n0-7,k8-15),(n8-15,k0-7),(n8-15,k8-15)
    const uint32_t bBase = stage + OFF_BH +
        (uint32_t)(((wn * 64 + (lane >> 4) * 8 + (lane & 7)) * TSTRIDE + ((lane >> 3) & 1) * 8) * 2);
    const uint32_t loA = OFF_AL - OFF_AH;
    const uint32_t loB = OFF_BL - OFF_BH;

#pragma unroll
    for (int kk = 0; kk < 32; kk += 16) {
        uint32_t afh[2][4], afl[2][4];
#pragma unroll
        for (int mt = 0; mt < 2; mt++) {
            uint32_t a = aBase + (uint32_t)((mt * 16 * TSTRIDE + kk) * 2);
            ldsm4(afh[mt], a);
            ldsm4(afl[mt], a + loA);
        }
#pragma unroll
        for (int np = 0; np < 4; np++) {
            uint32_t b = bBase + (uint32_t)((np * 16 * TSTRIDE + kk) * 2);
            uint32_t bh[4], bl[4];
            ldsm4(bh, b);
            ldsm4(bl, b + loB);
#pragma unroll
            for (int mt = 0; mt < 2; mt++) {
                mma16816(acc[mt][np * 2],     afh[mt], &bh[0]);
                mma16816(acc[mt][np * 2 + 1], afh[mt], &bh[2]);
                mma16816(acc[mt][np * 2],     afl[mt], &bh[0]);
                mma16816(acc[mt][np * 2 + 1], afl[mt], &bh[2]);
                mma16816(acc[mt][np * 2],     afh[mt], &bl[0]);
                mma16816(acc[mt][np * 2 + 1], afh[mt], &bl[2]);
            }
        }
    }
}

// ======================= SAGE layer GEMM =======================
template <int K>
__global__ __launch_bounds__(512, 1)
void sage_mma(const __nv_bfloat16* __restrict__ agg2, const __nv_bfloat16* __restrict__ h2,
              const __nv_bfloat16* __restrict__ Wl2, const __nv_bfloat16* __restrict__ Wr2,
              const float* __restrict__ bias, __nv_bfloat16* __restrict__ out2, int mode) {
    extern __shared__ __nv_bfloat16 smdyn[];
    const uint32_t smbase = smem_u32(smdyn);

    const int tid = threadIdx.x;
    const int wid = tid >> 5, lane = tid & 31;
    const int wm = wid & 3, wn = wid >> 2;       // 4 x 4 warps
    const int lr = lane >> 2, lq = lane & 3;
    const int bm = blockIdx.x * 128;
    constexpr int K2 = 2 * K;
    constexpr int CPS = K / 32;
    constexpr int NCH = 2 * CPS;

    const int pr = tid >> 2;                     // 0..127
    const int pc = (tid & 3) * 8;                // bf16 col in 32-chunk

    float acc[2][8][4];
#pragma unroll
    for (int i = 0; i < 2; i++)
#pragma unroll
        for (int j = 0; j < 8; j++)
#pragma unroll
            for (int t = 0; t < 4; t++) acc[i][j][t] = 0.0f;

    auto prefetch = [&](int ci, int b) {
        const __nv_bfloat16* Asrc = (ci < CPS) ? agg2 : h2;
        const __nv_bfloat16* Bsrc = (ci < CPS) ? Wl2 : Wr2;
        int c = ci & (CPS - 1);
        uint32_t sb = smbase + (uint32_t)b * STAGE_BYTES;
        uint32_t so = (uint32_t)(pr * TSTRIDE + pc) * 2;
        const __nv_bfloat16* Ap = Asrc + (size_t)(bm + pr) * K2 + c * 32 + pc;
        cpa16(sb + OFF_AH + so, Ap);
        cpa16(sb + OFF_AL + so, Ap + K);
#pragma unroll
        for (int half = 0; half < 2; half++) {
            int rr = pr + half * 128;
            uint32_t so2 = (uint32_t)(rr * TSTRIDE + pc) * 2;
            const __nv_bfloat16* Bp = Bsrc + (size_t)rr * K2 + c * 32 + pc;
            cpa16(sb + OFF_BH + so2, Bp);
            cpa16(sb + OFF_BL + so2, Bp + K);
        }
        CPA_COMMIT();
    };

    prefetch(0, 0);
    for (int i = 0; i < NCH; i++) {
        int b = i & 1;
        if (i + 1 < NCH) { prefetch(i + 1, b ^ 1); CPA_WAIT1(); }
        else             { CPA_WAIT0(); }
        __syncthreads();
        gemm_chunk(smbase + (uint32_t)b * STAGE_BYTES, wm, wn, lane, acc);
        __syncthreads();
    }

    // epilogue: bias + relu + hi/lo split
#pragma unroll
    for (int mt = 0; mt < 2; mt++) {
#pragma unroll
        for (int nt = 0; nt < 8; nt++) {
            int col = wn * 64 + nt * 8 + lq * 2;
            float bs0 = __ldg(&bias[col]), bs1 = __ldg(&bias[col + 1]);
#pragma unroll
            for (int half = 0; half < 2; half++) {
                int grow = bm + wm * 32 + mt * 16 + lr + half * 8;
                float v0 = fmaxf(acc[mt][nt][half * 2 + 0] + bs0, 0.0f);
                float v1 = fmaxf(acc[mt][nt][half * 2 + 1] + bs1, 0.0f);
                __nv_bfloat16 h0, l0, h1, l1;
                split_bf16(v0, h0, l0);
                split_bf16(v1, h1, l1);
                if (mode == 0) {
                    *reinterpret_cast<__nv_bfloat162*>(&out2[(size_t)grow * 512 + col]) =
                        __nv_bfloat162{h0, h1};
                    *reinterpret_cast<__nv_bfloat162*>(&out2[(size_t)grow * 512 + 256 + col]) =
                        __nv_bfloat162{l0, l1};
                } else {
                    int R = grow >> 5;
                    int m = ((grow & 31) << 8) + col;
                    *reinterpret_cast<__nv_bfloat162*>(&out2[(size_t)R * 16384 + m]) =
                        __nv_bfloat162{h0, h1};
                    *reinterpret_cast<__nv_bfloat162*>(&out2[(size_t)R * 16384 + 8192 + m]) =
                        __nv_bfloat162{l0, l1};
                }
            }
        }
    }
}

// ======================= mlp1 GEMM (split-K=8, atomic accum) ============
__global__ __launch_bounds__(512, 1)
void mlp1_mma(const __nv_bfloat16* __restrict__ A2, const __nv_bfloat16* __restrict__ W2t,
              float* __restrict__ C) {
    extern __shared__ __nv_bfloat16 smdyn[];
    const uint32_t smbase = smem_u32(smdyn);

    const int tid = threadIdx.x;
    const int wid = tid >> 5, lane = tid & 31;
    const int wm = wid & 3, wn = wid >> 2;
    const int lr = lane >> 2, lq = lane & 3;
    const int bm = blockIdx.x * 128;
    const int g0 = blockIdx.z * 32;
    const int NCH = 32;

    const int pr = tid >> 2;
    const int pc = (tid & 3) * 8;

    float acc[2][8][4];
#pragma unroll
    for (int i = 0; i < 2; i++)
#pragma unroll
        for (int j = 0; j < 8; j++)
#pragma unroll
            for (int t = 0; t < 4; t++) acc[i][j][t] = 0.0f;

    auto prefetch = [&](int i, int b) {
        int c = g0 + i;
        uint32_t sb = smbase + (uint32_t)b * STAGE_BYTES;
        uint32_t so = (uint32_t)(pr * TSTRIDE + pc) * 2;
        const __nv_bfloat16* Ap = A2 + (size_t)(bm + pr) * 16384 + c * 32 + pc;
        cpa16(sb + OFF_AH + so, Ap);
        cpa16(sb + OFF_AL + so, Ap + 8192);
#pragma unroll
        for (int half = 0; half < 2; half++) {
            int rr = pr + half * 128;
            uint32_t so2 = (uint32_t)(rr * TSTRIDE + pc) * 2;
            const __nv_bfloat16* Bp = W2t + (size_t)rr * 16384 + c * 32 + pc;
            cpa16(sb + OFF_BH + so2, Bp);
            cpa16(sb + OFF_BL + so2, Bp + 8192);
        }
        CPA_COMMIT();
    };

    prefetch(0, 0);
    for (int i = 0; i < NCH; i++) {
        int b = i & 1;
        if (i + 1 < NCH) { prefetch(i + 1, b ^ 1); CPA_WAIT1(); }
        else             { CPA_WAIT0(); }
        __syncthreads();
        gemm_chunk(smbase + (uint32_t)b * STAGE_BYTES, wm, wn, lane, acc);
        __syncthreads();
    }

#pragma unroll
    for (int mt = 0; mt < 2; mt++) {
#pragma unroll
        for (int nt = 0; nt < 8; nt++) {
            int col = wn * 64 + nt * 8 + lq * 2;
#pragma unroll
            for (int half = 0; half < 2; half++) {
                int row = bm + wm * 32 + mt * 16 + lr + half * 8;
                atomicAdd(&C[(size_t)row * 256 + col],     acc[mt][nt][half * 2 + 0]);
                atomicAdd(&C[(size_t)row * 256 + col + 1], acc[mt][nt][half * 2 + 1]);
            }
        }
    }
}

// ======================= tail kernels =======================
__global__ void mlp1_finalize(const float* __restrict__ M1, const float* __restrict__ b1,
                              const float* __restrict__ W2, const float* __restrict__ b2,
                              float* __restrict__ y) {
    int row = (blockIdx.x * blockDim.x + threadIdx.x) >> 5;
    int lane = threadIdx.x & 31;
    if (row >= MROW) return;
    float s = 0.0f;
    for (int c = lane; c < HD; c += 32)
        s += fmaxf(M1[row * HD + c] + b1[c], 0.0f) * W2[c];
#pragma unroll
    for (int o = 16; o; o >>= 1) s += __shfl_xor_sync(0xffffffffu, s, o);
    if (lane == 0) y[row] = s + b2[0];
}

__global__ void bn_kernel(const float* __restrict__ y, const float* __restrict__ gamma,
                          const float* __restrict__ beta, float* __restrict__ ybn) {
    int hh = threadIdx.x;
    float v[NB];
    float m = 0.0f;
#pragma unroll
    for (int b = 0; b < NB; b++) { v[b] = y[b * HD + hh]; m += v[b]; }
    m *= (1.0f / NB);
    float var = 0.0f;
#pragma unroll
    for (int b = 0; b < NB; b++) { float d = v[b] - m; var += d * d; }
    var *= (1.0f / NB);
    float inv = rsqrtf(var + 1e-5f) * gamma[hh];
    float be = beta[hh];
#pragma unroll
    for (int b = 0; b < NB; b++)
        ybn[b * HD + hh] = fmaxf((v[b] - m) * inv + be, 0.0f);
}

__global__ void mlp2a(const float* __restrict__ ybn, const float* __restrict__ W1,
                      const float* __restrict__ b1, float* __restrict__ z) {
    int b = blockIdx.x;
    int j = threadIdx.x;
    __shared__ float row[HD];
    row[j] = ybn[b * HD + j];
    __syncthreads();
    float s = b1[j];
    for (int hh = 0; hh < HD; hh++) s += row[hh] * W1[hh * HD + j];
    z[b * HD + j] = fmaxf(s, 0.0f);
}

__global__ void mlp2b(const float* __restrict__ z, const float* __restrict__ W2,
                      const float* __restrict__ b2, float* __restrict__ out) {
    int t = threadIdx.x;
    if (t >= NB * 8) return;
    int b = t >> 3, o = t & 7;
    float s = b2[o];
    for (int j = 0; j < HD; j++) s += z[b * HD + j] * W2[j * 8 + o];
    out[t] = s;
}

// ======================= host launch =======================
extern "C" void kernel_launch(void* const* d_in, const int* in_sizes, int n_in,
                              void* d_out, int out_size) {
    const float* x    = (const float*)d_in[0];
    const float* g0   = (const float*)d_in[1];
    const float* g1   = (const float*)d_in[2];
    const float* g2   = (const float*)d_in[3];
    const int*   esrc = (const int*)d_in[4];
    const int*   edst = (const int*)d_in[5];
    const float* Wl0  = (const float*)d_in[6];
    const float* Wr0  = (const float*)d_in[7];
    const float* b0   = (const float*)d_in[8];
    const float* Wl1  = (const float*)d_in[9];
    const float* Wr1  = (const float*)d_in[10];
    const float* b1   = (const float*)d_in[11];
    const float* Wl2  = (const float*)d_in[12];
    const float* Wr2  = (const float*)d_in[13];
    const float* b2   = (const float*)d_in[14];
    const float* Wl3  = (const float*)d_in[15];
    const float* Wr3  = (const float*)d_in[16];
    const float* b3   = (const float*)d_in[17];
    const float* m1W1 = (const float*)d_in[18];
    const float* m1b1 = (const float*)d_in[19];
    const float* m1W2 = (const float*)d_in[20];
    const float* m1b2 = (const float*)d_in[21];
    const float* gam  = (const float*)d_in[22];
    const float* bet  = (const float*)d_in[23];
    const float* m2W1 = (const float*)d_in[24];
    const float* m2b1 = (const float*)d_in[25];
    const float* m2W2 = (const float*)d_in[26];
    const float* m2b2 = (const float*)d_in[27];

    __nv_bfloat16 *h02, *agg2, *h2A, *h2B, *m1A2, *w2, *m1w2;
    int *cnt, *cur;
    float *m1, *y, *ybn, *z;
    cudaGetSymbolAddress((void**)&h02, d_h02);
    cudaGetSymbolAddress((void**)&agg2, d_agg2);
    cudaGetSymbolAddress((void**)&h2A, d_h2A);
    cudaGetSymbolAddress((void**)&h2B, d_h2B);
    cudaGetSymbolAddress((void**)&m1A2, d_m1A2);
    cudaGetSymbolAddress((void**)&w2, d_w2);
    cudaGetSymbolAddress((void**)&m1w2, d_m1w2);
    cudaGetSymbolAddress((void**)&cnt, d_cnt);
    cudaGetSymbolAddress((void**)&cur, d_cur);
    cudaGetSymbolAddress((void**)&m1, d_m1);
    cudaGetSymbolAddress((void**)&y, d_y);
    cudaGetSymbolAddress((void**)&ybn, d_ybn);
    cudaGetSymbolAddress((void**)&z, d_z);

    cudaFuncSetAttribute(sage_mma<128>, cudaFuncAttributeMaxDynamicSharedMemorySize, GEMM_SMEM_BYTES);
    cudaFuncSetAttribute(sage_mma<256>, cudaFuncAttributeMaxDynamicSharedMemorySize, GEMM_SMEM_BYTES);
    cudaFuncSetAttribute(mlp1_mma,      cudaFuncAttributeMaxDynamicSharedMemorySize, GEMM_SMEM_BYTES);

    __nv_bfloat16* wl[4] = {w2 + 0 * 256 * 512, w2 + 2 * 256 * 512, w2 + 4 * 256 * 512, w2 + 6 * 256 * 512};
    __nv_bfloat16* wr[4] = {w2 + 1 * 256 * 512, w2 + 3 * 256 * 512, w2 + 5 * 256 * 512, w2 + 7 * 256 * 512};

    conv_w<<<128, 256>>>(Wl0, wl[0], 128);
    conv_w<<<128, 256>>>(Wr0, wr[0], 128);
    conv_w<<<256, 256>>>(Wl1, wl[1], 256);
    conv_w<<<256, 256>>>(Wr1, wr[1], 256);
    conv_w<<<256, 256>>>(Wl2, wl[2], 256);
    conv_w<<<256, 256>>>(Wr2, wr[2], 256);
    conv_w<<<256, 256>>>(Wl3, wl[3], 256);
    conv_w<<<256, 256>>>(Wr3, wr[3], 256);
    conv_w<<<8192, 256>>>(m1W1, m1w2, 8192);

    concat2_kernel<<<(NN * 128) / 256, 256>>>(x, g0, g1, g2);
    zero_i<<<NN / 256, 256>>>(cnt, NN);
    count_kernel<<<EE / 256, 256>>>(edst);
    invcnt_kernel<<<NN / 256, 256>>>();
    scan_kernel<<<1, 1024>>>();
    zero_i<<<NN / 256, 256>>>(cur, NN);
    fill_kernel<<<EE / 256, 256>>>(esrc, edst);

    agg_csr<128><<<NN / 8, 256>>>(h02, agg2);
    sage_mma<128><<<NN / 128, 512, GEMM_SMEM_BYTES>>>(agg2, h02, wl[0], wr[0], b0, h2A, 0);
    agg_csr<256><<<NN / 8, 256>>>(h2A, agg2);
    sage_mma<256><<<NN / 128, 512, GEMM_SMEM_BYTES>>>(agg2, h2A, wl[1], wr[1], b1, h2B, 0);
    agg_csr<256><<<NN / 8, 256>>>(h2B, agg2);
    sage_mma<256><<<NN / 128, 512, GEMM_SMEM_BYTES>>>(agg2, h2B, wl[2], wr[2], b2, h2A, 0);
    agg_csr<256><<<NN / 8, 256>>>(h2A, agg2);
    sage_mma<256><<<NN / 128, 512, GEMM_SMEM_BYTES>>>(agg2, h2A, wl[3], wr[3], b3, m1A2, 1);

    zero_f<<<(MROW * HD) / 256, 256>>>(m1, MROW * HD);
    mlp1_mma<<<dim3(MROW / 128, 1, 8), 512, GEMM_SMEM_BYTES>>>(m1A2, m1w2, m1);
    mlp1_finalize<<<MROW / 8, 256>>>(m1, m1b1, m1W2, m1b2, y);

    bn_kernel<<<1, 256>>>(y, gam, bet, ybn);
    mlp2a<<<NB, 256>>>(ybn, m2W1, m2b1, z);
    mlp2b<<<1, 64>>>(z, m2W2, m2b2, (float*)d_out);
}

// round 7
// speedup vs baseline: 1.1183x; 1.1183x over previous
#include <cuda_runtime.h>
#include <cuda_bf16.h>
#include <cstdint>

#define NN   65536
#define EE   524288
#define DIN  128
#define HD   256
#define NB   8
#define MROW 2048   // NB * HD

// ======================= helpers =======================
__device__ __forceinline__ void split_bf16(float v, __nv_bfloat16& h, __nv_bfloat16& l) {
    h = __float2bfloat16(v);
    l = __float2bfloat16(v - __bfloat162float(h));
}

__device__ __forceinline__ void mma16816(float* c, const uint32_t* a, const uint32_t* b) {
    asm volatile(
        "mma.sync.aligned.m16n8k16.row.col.f32.bf16.bf16.f32 "
        "{%0,%1,%2,%3}, {%4,%5,%6,%7}, {%8,%9}, {%0,%1,%2,%3};"
        : "+f"(c[0]), "+f"(c[1]), "+f"(c[2]), "+f"(c[3])
        : "r"(a[0]), "r"(a[1]), "r"(a[2]), "r"(a[3]), "r"(b[0]), "r"(b[1]));
}

__device__ __forceinline__ void ldsm4(uint32_t* r, uint32_t addr) {
    asm volatile("ldmatrix.sync.aligned.m8n8.x4.shared.b16 {%0,%1,%2,%3}, [%4];"
        : "=r"(r[0]), "=r"(r[1]), "=r"(r[2]), "=r"(r[3]) : "r"(addr));
}

__device__ __forceinline__ uint32_t smem_u32(const void* p) {
    uint32_t a;
    asm("{ .reg .u64 t; cvta.to.shared.u64 t, %1; cvt.u32.u64 %0, t; }" : "=r"(a) : "l"(p));
    return a;
}

__device__ __forceinline__ void cpa16(uint32_t dst, const void* src) {
    asm volatile("cp.async.cg.shared.global [%0], [%1], 16;" :: "r"(dst), "l"(src));
}
#define CPA_COMMIT() asm volatile("cp.async.commit_group;" ::: "memory")
#define CPA_WAIT1()  asm volatile("cp.async.wait_group 1;" ::: "memory")
#define CPA_WAIT0()  asm volatile("cp.async.wait_group 0;" ::: "memory")

// smem tiling (R5 layout): 4 tiles (Ah, Al, Bh, Bl), each 128 rows x 40 bf16
#define TSTRIDE 40
#define TE (128 * TSTRIDE)              // elements per tile
#define BUFE (4 * TE)                   // elements per stage buffer
#define STAGE_BYTES (BUFE * 2)          // 40960
#define GEMM_SMEM_BYTES (2 * STAGE_BYTES)  // 81920
#define OFFB_AH 0
#define OFFB_AL (TE * 2)
#define OFFB_BH (2 * TE * 2)
#define OFFB_BL (3 * TE * 2)

// ======================= static device scratch =======================
__device__ __nv_bfloat16 d_h02[NN * 256];
__device__ __nv_bfloat16 d_agg2[NN * 512];
__device__ __nv_bfloat16 d_h2A[NN * 512];
__device__ __nv_bfloat16 d_h2B[NN * 512];
__device__ __nv_bfloat16 d_m1A2[(size_t)MROW * 16384];
__device__ __nv_bfloat16 d_w2[8][256 * 512];
__device__ __nv_bfloat16 d_m1w2[(size_t)256 * 16384];
__device__ int   d_cnt[NN];
__device__ int   d_off[NN + 1];
__device__ int   d_cur[NN];
__device__ int   d_csr[EE];
__device__ float d_invcnt[NN];
__device__ float d_m1[MROW * HD];
__device__ float d_y[MROW];
__device__ float d_ybn[NB * HD];
__device__ float d_z[NB * HD];

// ======================= small kernels =======================
__global__ void zero_f(float* __restrict__ p, int n) {
    int i = blockIdx.x * blockDim.x + threadIdx.x;
    if (i < n) p[i] = 0.0f;
}
__global__ void zero_i(int* __restrict__ p, int n) {
    int i = blockIdx.x * blockDim.x + threadIdx.x;
    if (i < n) p[i] = 0;
}

__global__ void concat2_kernel(const float* __restrict__ x, const float* __restrict__ g0,
                               const float* __restrict__ g1, const float* __restrict__ g2) {
    int i = blockIdx.x * blockDim.x + threadIdx.x;
    if (i >= NN * 128) return;
    int n = i >> 7, j = i & 127;
    float v;
    if (j < 32)       v = x[n * 32 + j];
    else if (j < 64)  v = g0[n * 32 + (j - 32)];
    else if (j < 96)  v = g1[n * 32 + (j - 64)];
    else              v = g2[n * 32 + (j - 96)];
    __nv_bfloat16 h, l; split_bf16(v, h, l);
    d_h02[n * 256 + j]       = h;
    d_h02[n * 256 + 128 + j] = l;
}

__global__ void conv_w(const float* __restrict__ W, __nv_bfloat16* __restrict__ out, int K) {
    int i = blockIdx.x * blockDim.x + threadIdx.x;
    if (i >= K * 256) return;
    int n = i & 255, k = i >> 8;
    float v = W[k * 256 + n];
    __nv_bfloat16 h, l; split_bf16(v, h, l);
    out[(size_t)n * 2 * K + k]     = h;
    out[(size_t)n * 2 * K + K + k] = l;
}

__global__ void count_kernel(const int* __restrict__ dst) {
    int e = blockIdx.x * blockDim.x + threadIdx.x;
    if (e < EE) atomicAdd(&d_cnt[dst[e]], 1);
}

__global__ void invcnt_kernel() {
    int n = blockIdx.x * blockDim.x + threadIdx.x;
    if (n < NN) d_invcnt[n] = 1.0f / fmaxf((float)d_cnt[n], 1.0f);
}

__global__ void scan_kernel() {
    __shared__ int s[1024];
    int t = threadIdx.x;
    int base = t * 64;
    int sum = 0;
    for (int i = 0; i < 64; i++) sum += d_cnt[base + i];
    s[t] = sum;
    __syncthreads();
    for (int o = 1; o < 1024; o <<= 1) {
        int v = (t >= o) ? s[t - o] : 0;
        __syncthreads();
        s[t] += v;
        __syncthreads();
    }
    int run = s[t] - sum;
    for (int i = 0; i < 64; i++) { d_off[base + i] = run; run += d_cnt[base + i]; }
    if (t == 1023) d_off[NN] = run;
}

__global__ void fill_kernel(const int* __restrict__ src, const int* __restrict__ dst) {
    int e = blockIdx.x * blockDim.x + threadIdx.x;
    if (e >= EE) return;
    int d = dst[e];
    int p = atomicAdd(&d_cur[d], 1);
    d_csr[d_off[d] + p] = src[e];
}

// CSR mean-aggregation: warp per node. Rows are [hi(D) | lo(D)] bf16.
template <int D>
__global__ void agg_csr(const __nv_bfloat16* __restrict__ H2,
                        __nv_bfloat16* __restrict__ out2) {
    int w = (blockIdx.x * blockDim.x + threadIdx.x) >> 5;
    int lane = threadIdx.x & 31;
    if (w >= NN) return;
    int s0 = __ldg(&d_off[w]), s1 = __ldg(&d_off[w + 1]);
    constexpr int R = D / 64;
    float a0[R], a1[R];
#pragma unroll
    for (int r = 0; r < R; r++) { a0[r] = 0.0f; a1[r] = 0.0f; }
    for (int p = s0; p < s1; p++) {
        int nb = __ldg(&d_csr[p]);
        const __nv_bfloat16* base = H2 + (size_t)nb * (2 * D);
#pragma unroll
        for (int r = 0; r < R; r++) {
            int c2 = (lane + r * 32) * 2;
            __nv_bfloat162 hv = *reinterpret_cast<const __nv_bfloat162*>(base + c2);
            __nv_bfloat162 lv = *reinterpret_cast<const __nv_bfloat162*>(base + D + c2);
            float2 hf = __bfloat1622float2(hv);
            float2 lf = __bfloat1622float2(lv);
            a0[r] += hf.x + lf.x;
            a1[r] += hf.y + lf.y;
        }
    }
    float ic = d_invcnt[w];
    __nv_bfloat16* ob = out2 + (size_t)w * (2 * D);
#pragma unroll
    for (int r = 0; r < R; r++) {
        float v0 = a0[r] * ic, v1 = a1[r] * ic;
        __nv_bfloat16 h0, l0, h1, l1;
        split_bf16(v0, h0, l0);
        split_bf16(v1, h1, l1);
        int c2 = (lane + r * 32) * 2;
        *reinterpret_cast<__nv_bfloat162*>(ob + c2)     = __nv_bfloat162{h0, h1};
        *reinterpret_cast<__nv_bfloat162*>(ob + D + c2) = __nv_bfloat162{l0, l1};
    }
}

// ======================= GEMM compute core (ldmatrix, R5 block shape) =============
// Block: 256 threads, 8 warps (4m x 2n). Warp tile 32 x 64. Chunk = 32 K-cols.
__device__ __forceinline__ void gemm_chunk(uint32_t stage, int wm, int wn, int lane,
                                           float acc[2][8][4]) {
    const uint32_t aBase = stage + OFFB_AH +
        (uint32_t)(((wm * 32 + (lane & 15)) * TSTRIDE + (lane >> 4) * 8) * 2);
    const uint32_t bBase = stage + OFFB_BH +
        (uint32_t)(((wn * 64 + (lane >> 4) * 8 + (lane & 7)) * TSTRIDE + ((lane >> 3) & 1) * 8) * 2);
    const uint32_t loA = OFFB_AL - OFFB_AH;
    const uint32_t loB = OFFB_BL - OFFB_BH;

#pragma unroll
    for (int kk = 0; kk < 32; kk += 16) {
        uint32_t afh[2][4], afl[2][4];
#pragma unroll
        for (int mt = 0; mt < 2; mt++) {
            uint32_t a = aBase + (uint32_t)((mt * 16 * TSTRIDE + kk) * 2);
            ldsm4(afh[mt], a);
            ldsm4(afl[mt], a + loA);
        }
#pragma unroll
        for (int np = 0; np < 4; np++) {
            uint32_t b = bBase + (uint32_t)((np * 16 * TSTRIDE + kk) * 2);
            uint32_t bh[4], bl[4];
            ldsm4(bh, b);
            ldsm4(bl, b + loB);
#pragma unroll
            for (int mt = 0; mt < 2; mt++) {
                mma16816(acc[mt][np * 2],     afh[mt], &bh[0]);
                mma16816(acc[mt][np * 2 + 1], afh[mt], &bh[2]);
                mma16816(acc[mt][np * 2],     afl[mt], &bh[0]);
                mma16816(acc[mt][np * 2 + 1], afl[mt], &bh[2]);
                mma16816(acc[mt][np * 2],     afh[mt], &bl[0]);
                mma16816(acc[mt][np * 2 + 1], afh[mt], &bl[2]);
            }
        }
    }
}

// ======================= SAGE layer GEMM (cp.async double-buffered) ===============
template <int K>
__global__ __launch_bounds__(256, 2)
void sage_mma(const __nv_bfloat16* __restrict__ agg2, const __nv_bfloat16* __restrict__ h2,
              const __nv_bfloat16* __restrict__ Wl2, const __nv_bfloat16* __restrict__ Wr2,
              const float* __restrict__ bias, __nv_bfloat16* __restrict__ out2, int mode) {
    extern __shared__ __nv_bfloat16 smdyn[];
    const uint32_t smbase = smem_u32(smdyn);

    const int tid = threadIdx.x;
    const int wid = tid >> 5, lane = tid & 31;
    const int wm = wid & 3, wn = wid >> 2;
    const int lr = lane >> 2, lq = lane & 3;
    const int bm = blockIdx.x * 128;
    const int bn = blockIdx.y * 128;
    constexpr int K2 = 2 * K;
    constexpr int CPS = K / 32;
    constexpr int NCH = 2 * CPS;

    const int r0 = tid >> 2;          // 0..63
    const int cb = (tid & 3) * 8;

    float acc[2][8][4];
#pragma unroll
    for (int i = 0; i < 2; i++)
#pragma unroll
        for (int j = 0; j < 8; j++)
#pragma unroll
            for (int t = 0; t < 4; t++) acc[i][j][t] = 0.0f;

    auto prefetch = [&](int ci, int b) {
        const __nv_bfloat16* Asrc = (ci < CPS) ? agg2 : h2;
        const __nv_bfloat16* Bsrc = (ci < CPS) ? Wl2 : Wr2;
        int c = ci & (CPS - 1);
        uint32_t sb = smbase + (uint32_t)b * STAGE_BYTES;
#pragma unroll
        for (int half = 0; half < 2; half++) {
            int r = r0 + half * 64;
            uint32_t so = (uint32_t)(r * TSTRIDE + cb) * 2;
            const __nv_bfloat16* Ap = Asrc + (size_t)(bm + r) * K2 + c * 32 + cb;
            const __nv_bfloat16* Bp = Bsrc + (size_t)(bn + r) * K2 + c * 32 + cb;
            cpa16(sb + OFFB_AH + so, Ap);
            cpa16(sb + OFFB_AL + so, Ap + K);
            cpa16(sb + OFFB_BH + so, Bp);
            cpa16(sb + OFFB_BL + so, Bp + K);
        }
        CPA_COMMIT();
    };

    prefetch(0, 0);
    for (int i = 0; i < NCH; i++) {
        int b = i & 1;
        if (i + 1 < NCH) { prefetch(i + 1, b ^ 1); CPA_WAIT1(); }
        else             { CPA_WAIT0(); }
        __syncthreads();
        gemm_chunk(smbase + (uint32_t)b * STAGE_BYTES, wm, wn, lane, acc);
        __syncthreads();
    }

    // epilogue: bias + relu + hi/lo split
#pragma unroll
    for (int mt = 0; mt < 2; mt++) {
#pragma unroll
        for (int nt = 0; nt < 8; nt++) {
            int col = bn + wn * 64 + nt * 8 + lq * 2;
            float bs0 = __ldg(&bias[col]), bs1 = __ldg(&bias[col + 1]);
#pragma unroll
            for (int half = 0; half < 2; half++) {
                int grow = bm + wm * 32 + mt * 16 + lr + half * 8;
                float v0 = fmaxf(acc[mt][nt][half * 2 + 0] + bs0, 0.0f);
                float v1 = fmaxf(acc[mt][nt][half * 2 + 1] + bs1, 0.0f);
                __nv_bfloat16 h0, l0, h1, l1;
                split_bf16(v0, h0, l0);
                split_bf16(v1, h1, l1);
                if (mode == 0) {
                    *reinterpret_cast<__nv_bfloat162*>(&out2[(size_t)grow * 512 + col]) =
                        __nv_bfloat162{h0, h1};
                    *reinterpret_cast<__nv_bfloat162*>(&out2[(size_t)grow * 512 + 256 + col]) =
                        __nv_bfloat162{l0, l1};
                } else {
                    int R = grow >> 5;
                    int m = ((grow & 31) << 8) + col;
                    *reinterpret_cast<__nv_bfloat162*>(&out2[(size_t)R * 16384 + m]) =
                        __nv_bfloat162{h0, h1};
                    *reinterpret_cast<__nv_bfloat162*>(&out2[(size_t)R * 16384 + 8192 + m]) =
                        __nv_bfloat162{l0, l1};
                }
            }
        }
    }
}

// ======================= mlp1 GEMM (split-K=8, cp.async, atomic accum) ============
__global__ __launch_bounds__(256, 2)
void mlp1_mma(const __nv_bfloat16* __restrict__ A2, const __nv_bfloat16* __restrict__ W2t,
              float* __restrict__ C) {
    extern __shared__ __nv_bfloat16 smdyn[];
    const uint32_t smbase = smem_u32(smdyn);

    const int tid = threadIdx.x;
    const int wid = tid >> 5, lane = tid & 31;
    const int wm = wid & 3, wn = wid >> 2;
    const int lr = lane >> 2, lq = lane & 3;
    const int bm = blockIdx.x * 128;
    const int bn = blockIdx.y * 128;
    const int g0 = blockIdx.z * 32;
    const int NCH = 32;

    const int r0 = tid >> 2;
    const int cb = (tid & 3) * 8;

    float acc[2][8][4];
#pragma unroll
    for (int i = 0; i < 2; i++)
#pragma unroll
        for (int j = 0; j < 8; j++)
#pragma unroll
            for (int t = 0; t < 4; t++) acc[i][j][t] = 0.0f;

    auto prefetch = [&](int i, int b) {
        int c = g0 + i;
        uint32_t sb = smbase + (uint32_t)b * STAGE_BYTES;
#pragma unroll
        for (int half = 0; half < 2; half++) {
            int r = r0 + half * 64;
            uint32_t so = (uint32_t)(r * TSTRIDE + cb) * 2;
            const __nv_bfloat16* Ap = A2 + (size_t)(bm + r) * 16384 + c * 32 + cb;
            const __nv_bfloat16* Bp = W2t + (size_t)(bn + r) * 16384 + c * 32 + cb;
            cpa16(sb + OFFB_AH + so, Ap);
            cpa16(sb + OFFB_AL + so, Ap + 8192);
            cpa16(sb + OFFB_BH + so, Bp);
            cpa16(sb + OFFB_BL + so, Bp + 8192);
        }
        CPA_COMMIT();
    };

    prefetch(0, 0);
    for (int i = 0; i < NCH; i++) {
        int b = i & 1;
        if (i + 1 < NCH) { prefetch(i + 1, b ^ 1); CPA_WAIT1(); }
        else             { CPA_WAIT0(); }
        __syncthreads();
        gemm_chunk(smbase + (uint32_t)b * STAGE_BYTES, wm, wn, lane, acc);
        __syncthreads();
    }

#pragma unroll
    for (int mt = 0; mt < 2; mt++) {
#pragma unroll
        for (int nt = 0; nt < 8; nt++) {
            int col = bn + wn * 64 + nt * 8 + lq * 2;
#pragma unroll
            for (int half = 0; half < 2; half++) {
                int row = bm + wm * 32 + mt * 16 + lr + half * 8;
                atomicAdd(&C[(size_t)row * 256 + col],     acc[mt][nt][half * 2 + 0]);
                atomicAdd(&C[(size_t)row * 256 + col + 1], acc[mt][nt][half * 2 + 1]);
            }
        }
    }
}

// ======================= tail kernels =======================
__global__ void mlp1_finalize(const float* __restrict__ M1, const float* __restrict__ b1,
                              const float* __restrict__ W2, const float* __restrict__ b2,
                              float* __restrict__ y) {
    int row = (blockIdx.x * blockDim.x + threadIdx.x) >> 5;
    int lane = threadIdx.x & 31;
    if (row >= MROW) return;
    float s = 0.0f;
    for (int c = lane; c < HD; c += 32)
        s += fmaxf(M1[row * HD + c] + b1[c], 0.0f) * W2[c];
#pragma unroll
    for (int o = 16; o; o >>= 1) s += __shfl_xor_sync(0xffffffffu, s, o);
    if (lane == 0) y[row] = s + b2[0];
}

__global__ void bn_kernel(const float* __restrict__ y, const float* __restrict__ gamma,
                          const float* __restrict__ beta, float* __restrict__ ybn) {
    int hh = threadIdx.x;
    float v[NB];
    float m = 0.0f;
#pragma unroll
    for (int b = 0; b < NB; b++) { v[b] = y[b * HD + hh]; m += v[b]; }
    m *= (1.0f / NB);
    float var = 0.0f;
#pragma unroll
    for (int b = 0; b < NB; b++) { float d = v[b] - m; var += d * d; }
    var *= (1.0f / NB);
    float inv = rsqrtf(var + 1e-5f) * gamma[hh];
    float be = beta[hh];
#pragma unroll
    for (int b = 0; b < NB; b++)
        ybn[b * HD + hh] = fmaxf((v[b] - m) * inv + be, 0.0f);
}

__global__ void mlp2a(const float* __restrict__ ybn, const float* __restrict__ W1,
                      const float* __restrict__ b1, float* __restrict__ z) {
    int b = blockIdx.x;
    int j = threadIdx.x;
    __shared__ float row[HD];
    row[j] = ybn[b * HD + j];
    __syncthreads();
    float s = b1[j];
    for (int hh = 0; hh < HD; hh++) s += row[hh] * W1[hh * HD + j];
    z[b * HD + j] = fmaxf(s, 0.0f);
}

__global__ void mlp2b(const float* __restrict__ z, const float* __restrict__ W2,
                      const float* __restrict__ b2, float* __restrict__ out) {
    int t = threadIdx.x;
    if (t >= NB * 8) return;
    int b = t >> 3, o = t & 7;
    float s = b2[o];
    for (int j = 0; j < HD; j++) s += z[b * HD + j] * W2[j * 8 + o];
    out[t] = s;
}

// ======================= host launch =======================
extern "C" void kernel_launch(void* const* d_in, const int* in_sizes, int n_in,
                              void* d_out, int out_size) {
    const float* x    = (const float*)d_in[0];
    const float* g0   = (const float*)d_in[1];
    const float* g1   = (const float*)d_in[2];
    const float* g2   = (const float*)d_in[3];
    const int*   esrc = (const int*)d_in[4];
    const int*   edst = (const int*)d_in[5];
    const float* Wl0  = (const float*)d_in[6];
    const float* Wr0  = (const float*)d_in[7];
    const float* b0   = (const float*)d_in[8];
    const float* Wl1  = (const float*)d_in[9];
    const float* Wr1  = (const float*)d_in[10];
    const float* b1   = (const float*)d_in[11];
    const float* Wl2  = (const float*)d_in[12];
    const float* Wr2  = (const float*)d_in[13];
    const float* b2   = (const float*)d_in[14];
    const float* Wl3  = (const float*)d_in[15];
    const float* Wr3  = (const float*)d_in[16];
    const float* b3   = (const float*)d_in[17];
    const float* m1W1 = (const float*)d_in[18];
    const float* m1b1 = (const float*)d_in[19];
    const float* m1W2 = (const float*)d_in[20];
    const float* m1b2 = (const float*)d_in[21];
    const float* gam  = (const float*)d_in[22];
    const float* bet  = (const float*)d_in[23];
    const float* m2W1 = (const float*)d_in[24];
    const float* m2b1 = (const float*)d_in[25];
    const float* m2W2 = (const float*)d_in[26];
    const float* m2b2 = (const float*)d_in[27];

    __nv_bfloat16 *h02, *agg2, *h2A, *h2B, *m1A2, *w2, *m1w2;
    int *cnt, *cur;
    float *m1, *y, *ybn, *z;
    cudaGetSymbolAddress((void**)&h02, d_h02);
    cudaGetSymbolAddress((void**)&agg2, d_agg2);
    cudaGetSymbolAddress((void**)&h2A, d_h2A);
    cudaGetSymbolAddress((void**)&h2B, d_h2B);
    cudaGetSymbolAddress((void**)&m1A2, d_m1A2);
    cudaGetSymbolAddress((void**)&w2, d_w2);
    cudaGetSymbolAddress((void**)&m1w2, d_m1w2);
    cudaGetSymbolAddress((void**)&cnt, d_cnt);
    cudaGetSymbolAddress((void**)&cur, d_cur);
    cudaGetSymbolAddress((void**)&m1, d_m1);
    cudaGetSymbolAddress((void**)&y, d_y);
    cudaGetSymbolAddress((void**)&ybn, d_ybn);
    cudaGetSymbolAddress((void**)&z, d_z);

    cudaFuncSetAttribute(sage_mma<128>, cudaFuncAttributeMaxDynamicSharedMemorySize, GEMM_SMEM_BYTES);
    cudaFuncSetAttribute(sage_mma<256>, cudaFuncAttributeMaxDynamicSharedMemorySize, GEMM_SMEM_BYTES);
    cudaFuncSetAttribute(mlp1_mma,      cudaFuncAttributeMaxDynamicSharedMemorySize, GEMM_SMEM_BYTES);

    __nv_bfloat16* wl[4] = {w2 + 0 * 256 * 512, w2 + 2 * 256 * 512, w2 + 4 * 256 * 512, w2 + 6 * 256 * 512};
    __nv_bfloat16* wr[4] = {w2 + 1 * 256 * 512, w2 + 3 * 256 * 512, w2 + 5 * 256 * 512, w2 + 7 * 256 * 512};

    conv_w<<<128, 256>>>(Wl0, wl[0], 128);
    conv_w<<<128, 256>>>(Wr0, wr[0], 128);
    conv_w<<<256, 256>>>(Wl1, wl[1], 256);
    conv_w<<<256, 256>>>(Wr1, wr[1], 256);
    conv_w<<<256, 256>>>(Wl2, wl[2], 256);
    conv_w<<<256, 256>>>(Wr2, wr[2], 256);
    conv_w<<<256, 256>>>(Wl3, wl[3], 256);
    conv_w<<<256, 256>>>(Wr3, wr[3], 256);
    conv_w<<<8192, 256>>>(m1W1, m1w2, 8192);

    concat2_kernel<<<(NN * 128) / 256, 256>>>(x, g0, g1, g2);
    zero_i<<<NN / 256, 256>>>(cnt, NN);
    count_kernel<<<EE / 256, 256>>>(edst);
    invcnt_kernel<<<NN / 256, 256>>>();
    scan_kernel<<<1, 1024>>>();
    zero_i<<<NN / 256, 256>>>(cur, NN);
    fill_kernel<<<EE / 256, 256>>>(esrc, edst);

    agg_csr<128><<<NN / 8, 256>>>(h02, agg2);
    sage_mma<128><<<dim3(NN / 128, 2), 256, GEMM_SMEM_BYTES>>>(agg2, h02, wl[0], wr[0], b0, h2A, 0);
    agg_csr<256><<<NN / 8, 256>>>(h2A, agg2);
    sage_mma<256><<<dim3(NN / 128, 2), 256, GEMM_SMEM_BYTES>>>(agg2, h2A, wl[1], wr[1], b1, h2B, 0);
    agg_csr<256><<<NN / 8, 256>>>(h2B, agg2);
    sage_mma<256><<<dim3(NN / 128, 2), 256, GEMM_SMEM_BYTES>>>(agg2, h2B, wl[2], wr[2], b2, h2A, 0);
    agg_csr<256><<<NN / 8, 256>>>(h2A, agg2);
    sage_mma<256><<<dim3(NN / 128, 2), 256, GEMM_SMEM_BYTES>>>(agg2, h2A, wl[3], wr[3], b3, m1A2, 1);

    zero_f<<<(MROW * HD) / 256, 256>>>(m1, MROW * HD);
    mlp1_mma<<<dim3(MROW / 128, 2, 8), 256, GEMM_SMEM_BYTES>>>(m1A2, m1w2, m1);
    mlp1_finalize<<<MROW / 8, 256>>>(m1, m1b1, m1W2, m1b2, y);

    bn_kernel<<<1, 256>>>(y, gam, bet, ybn);
    mlp2a<<<NB, 256>>>(ybn, m2W1, m2b1, z);
    mlp2b<<<1, 64>>>(z, m2W2, m2b2, (float*)d_out);
}